// round 17
// baseline (speedup 1.0000x reference)
#include <cuda_runtime.h>
#include <cuda_fp16.h>
#include <cstdint>

typedef unsigned int u32;

#define NN 50000
#define NE 800000
#define HEADS 8
#define H1DIM 128
#define OUTC 40
#define NEG 0.2f
#define GB1 391
#define CAP 128

// ---------------- scratch ----------------
__device__ __align__(16) __half2 g_h1h[NN * 64];
__device__ float g_as1[NN * HEADS];
__device__ float g_ad1[NN * HEADS];
__device__ float g_out1[NN * H1DIM];
__device__ __align__(16) __half2 g_h2h[NN * 20];
__device__ float g_as2[NN];
__device__ float g_ad2[NN];
__device__ int   g_cnt[NN];          // statically zero; node2 resets after use
__device__ int   g_bkt[NN * CAP];

__device__ __forceinline__ float leaky(float v) { return v > 0.f ? v : NEG * v; }
__device__ __forceinline__ float elu(float v) { return v > 0.f ? v : expm1f(v); }

__device__ __forceinline__ void ldsm_x4(u32& r0, u32& r1, u32& r2, u32& r3, u32 addr) {
    asm volatile("ldmatrix.sync.aligned.m8n8.x4.shared.b16 {%0,%1,%2,%3}, [%4];"
                 : "=r"(r0), "=r"(r1), "=r"(r2), "=r"(r3) : "r"(addr));
}
__device__ __forceinline__ void ldsm_x2_t(u32& r0, u32& r1, u32 addr) {
    asm volatile("ldmatrix.sync.aligned.m8n8.x2.trans.shared.b16 {%0,%1}, [%2];"
                 : "=r"(r0), "=r"(r1) : "r"(addr));
}
__device__ __forceinline__ void mma16816(float* c, const u32* a, u32 b0, u32 b1) {
    asm volatile("mma.sync.aligned.m16n8k16.row.col.f32.f16.f16.f32 "
                 "{%0,%1,%2,%3},{%4,%5,%6,%7},{%8,%9},{%0,%1,%2,%3};"
                 : "+f"(c[0]), "+f"(c[1]), "+f"(c[2]), "+f"(c[3])
                 : "r"(a[0]), "r"(a[1]), "r"(a[2]), "r"(a[3]), "r"(b0), "r"(b1));
}

// ---------------- FAT kernel: TC gemm1 (blocks < GB1) + bucket scatter (rest) ---
__global__ void __launch_bounds__(256) k_fat(
        const float* __restrict__ A, const float* __restrict__ B,
        const float* __restrict__ att_src, const float* __restrict__ att_dst,
        const int* __restrict__ ei) {
    __shared__ __half As[128][24];
    __shared__ __half Bs[16][136];
    if (blockIdx.x >= GB1) {
        int e = (blockIdx.x - GB1) * 256 + threadIdx.x;
        if (e < NE) {
            int s = ei[e];
            int d = ei[NE + e];
            int pos = atomicAdd(&g_cnt[d], 1);
            if (pos < CAP) g_bkt[d * CAP + pos] = s;
        }
        return;
    }
    int tid = threadIdx.x;
    int lane = tid & 31;
    int warp = tid >> 5;
    int m0 = (warp >> 1) * 32;
    int n0 = (warp & 1) * 64;
    int row0 = blockIdx.x * 128;
    u32 as_base = (u32)__cvta_generic_to_shared(&As[0][0]);
    u32 bs_base = (u32)__cvta_generic_to_shared(&Bs[0][0]);

    float acc[64];
#pragma unroll
    for (int i = 0; i < 64; i++) acc[i] = 0.f;

    for (int k0 = 0; k0 < 128; k0 += 16) {
        {
            int row = tid >> 1;
            int kp = (tid & 1) * 8;
            int grow = row0 + row;
            float4 v0 = make_float4(0.f, 0.f, 0.f, 0.f);
            float4 v1 = v0;
            if (grow < NN) {
                v0 = *(const float4*)&A[grow * 128 + k0 + kp];
                v1 = *(const float4*)&A[grow * 128 + k0 + kp + 4];
            }
            __half2 hh[4];
            hh[0] = __floats2half2_rn(v0.x, v0.y);
            hh[1] = __floats2half2_rn(v0.z, v0.w);
            hh[2] = __floats2half2_rn(v1.x, v1.y);
            hh[3] = __floats2half2_rn(v1.z, v1.w);
            *(uint4*)&As[row][kp] = *(uint4*)hh;
        }
        {
            int k = tid >> 4;
            int nn = (tid & 15) * 8;
            float4 w0 = *(const float4*)&B[(k0 + k) * 128 + nn];
            float4 w1 = *(const float4*)&B[(k0 + k) * 128 + nn + 4];
            __half2 hh[4];
            hh[0] = __floats2half2_rn(w0.x, w0.y);
            hh[1] = __floats2half2_rn(w0.z, w0.w);
            hh[2] = __floats2half2_rn(w1.x, w1.y);
            hh[3] = __floats2half2_rn(w1.z, w1.w);
            *(uint4*)&Bs[k][nn] = *(uint4*)hh;
        }
        __syncthreads();
        u32 a0[4];
        u32 a1[4];
        ldsm_x4(a0[0], a0[1], a0[2], a0[3],
                as_base + (u32)(m0 + (lane & 15)) * 48u + (u32)(lane >> 4) * 16u);
        ldsm_x4(a1[0], a1[1], a1[2], a1[3],
                as_base + (u32)(m0 + 16 + (lane & 15)) * 48u + (u32)(lane >> 4) * 16u);
#pragma unroll
        for (int t = 0; t < 8; t++) {
            u32 b0, b1;
            ldsm_x2_t(b0, b1, bs_base + (u32)(lane & 15) * 272u + (u32)(n0 + t * 8) * 2u);
            mma16816(&acc[t * 4], a0, b0, b1);
            mma16816(&acc[32 + t * 4], a1, b0, b1);
        }
        __syncthreads();
    }

    int g = lane >> 2;
    int q = lane & 3;
#pragma unroll
    for (int mt = 0; mt < 2; mt++) {
        int r0g = row0 + m0 + mt * 16 + g;
        int r1g = r0g + 8;
#pragma unroll
        for (int hx = 0; hx < 4; hx++) {
            float ps0 = 0.f;
            float ps1 = 0.f;
            float pd0 = 0.f;
            float pd1 = 0.f;
#pragma unroll
            for (int tt = 0; tt < 2; tt++) {
                int t = hx * 2 + tt;
                float* c = &acc[mt * 32 + t * 4];
                int col = n0 + t * 8 + q * 2;
                float w0 = att_src[col];
                float w1 = att_src[col + 1];
                float v0 = att_dst[col];
                float v1 = att_dst[col + 1];
                ps0 += c[0] * w0 + c[1] * w1;
                pd0 += c[0] * v0 + c[1] * v1;
                ps1 += c[2] * w0 + c[3] * w1;
                pd1 += c[2] * v0 + c[3] * v1;
                int h2i = (n0 + t * 8) / 2 + q;
                if (r0g < NN) g_h1h[r0g * 64 + h2i] = __floats2half2_rn(c[0], c[1]);
                if (r1g < NN) g_h1h[r1g * 64 + h2i] = __floats2half2_rn(c[2], c[3]);
            }
            ps0 += __shfl_xor_sync(0xffffffffu, ps0, 1);
            ps0 += __shfl_xor_sync(0xffffffffu, ps0, 2);
            ps1 += __shfl_xor_sync(0xffffffffu, ps1, 1);
            ps1 += __shfl_xor_sync(0xffffffffu, ps1, 2);
            pd0 += __shfl_xor_sync(0xffffffffu, pd0, 1);
            pd0 += __shfl_xor_sync(0xffffffffu, pd0, 2);
            pd1 += __shfl_xor_sync(0xffffffffu, pd1, 1);
            pd1 += __shfl_xor_sync(0xffffffffu, pd1, 2);
            if (q == 0) {
                int head = (n0 >> 4) + hx;
                if (r0g < NN) { g_as1[r0g * 8 + head] = ps0; g_ad1[r0g * 8 + head] = pd0; }
                if (r1g < NN) { g_as1[r1g * 8 + head] = ps1; g_ad1[r1g * 8 + head] = pd1; }
            }
        }
    }
}

// ---------------- layer1 node kernel: 4 edge-groups, 1 head (16ch) per lane -----
// grp = lane>>3 owns edge j+grp; hl = lane&7 is the head; channels hl*16..+16
__global__ void k_node1(const float* __restrict__ b1) {
    int lane = threadIdx.x & 31;
    int warp = (blockIdx.x * blockDim.x + threadIdx.x) >> 5;
    int nwarp = (gridDim.x * blockDim.x) >> 5;
    int grp = lane >> 3;
    int hl = lane & 7;
    for (int n = warp; n < NN; n += nwarp) {
        int cnt = g_cnt[n];
        if (cnt > CAP) cnt = CAP;
        int beg = n * CAP;
        float ad = g_ad1[n * 8 + hl];
        float acc[16];
#pragma unroll
        for (int i = 0; i < 16; i++) acc[i] = 0.f;
        float sum = 0.f;
        for (int base = 0; base < cnt; base += 32) {
            int c = cnt - base;
            if (c > 32) c = 32;
            int idx = (lane < c) ? g_bkt[beg + base + lane] : 0;
            for (int j = 0; j < c; j += 4) {
                int eIdx = j + grp;
                int src = (eIdx < 32) ? eIdx : 0;
                int s = __shfl_sync(0xffffffffu, idx, src);
                if (eIdx < c) {
                    float e = __expf(leaky(g_as1[s * 8 + hl] + ad));
                    sum += e;
                    uint4 r0 = *(const uint4*)&g_h1h[s * 64 + hl * 8];
                    uint4 r1 = *(const uint4*)&g_h1h[s * 64 + hl * 8 + 4];
                    float2 f;
                    f = __half22float2(*(const __half2*)&r0.x); acc[0] += e * f.x; acc[1] += e * f.y;
                    f = __half22float2(*(const __half2*)&r0.y); acc[2] += e * f.x; acc[3] += e * f.y;
                    f = __half22float2(*(const __half2*)&r0.z); acc[4] += e * f.x; acc[5] += e * f.y;
                    f = __half22float2(*(const __half2*)&r0.w); acc[6] += e * f.x; acc[7] += e * f.y;
                    f = __half22float2(*(const __half2*)&r1.x); acc[8] += e * f.x; acc[9] += e * f.y;
                    f = __half22float2(*(const __half2*)&r1.y); acc[10] += e * f.x; acc[11] += e * f.y;
                    f = __half22float2(*(const __half2*)&r1.z); acc[12] += e * f.x; acc[13] += e * f.y;
                    f = __half22float2(*(const __half2*)&r1.w); acc[14] += e * f.x; acc[15] += e * f.y;
                }
            }
        }
        // combine the 4 edge-groups (lanes differing in bits 3,4)
        sum += __shfl_xor_sync(0xffffffffu, sum, 8);
        sum += __shfl_xor_sync(0xffffffffu, sum, 16);
#pragma unroll
        for (int i = 0; i < 16; i++) {
            acc[i] += __shfl_xor_sync(0xffffffffu, acc[i], 8);
            acc[i] += __shfl_xor_sync(0xffffffffu, acc[i], 16);
        }
        float inv = (sum > 0.f) ? 1.f / sum : 0.f;
        if (grp == 0) {
#pragma unroll
            for (int v = 0; v < 4; v++) {
                float4 bv = *(const float4*)&b1[hl * 16 + v * 4];
                float4 o;
                o.x = elu(acc[v * 4 + 0] * inv + bv.x);
                o.y = elu(acc[v * 4 + 1] * inv + bv.y);
                o.z = elu(acc[v * 4 + 2] * inv + bv.z);
                o.w = elu(acc[v * 4 + 3] * inv + bv.w);
                *(float4*)&g_out1[n * 128 + hl * 16 + v * 4] = o;
            }
        }
    }
}

// ---------------- GEMM2 (tensor core): h2h = out1 @ W2 (fp16 store) + logits ----
__global__ void __launch_bounds__(256) k_gemm2(
        const float* __restrict__ B,
        const float* __restrict__ att_src, const float* __restrict__ att_dst) {
    __shared__ __half As[128][24];
    __shared__ __half Bs[16][72];
    int tid = threadIdx.x;
    int lane = tid & 31;
    int warp = tid >> 5;
    int m0 = warp * 16;
    int row0 = blockIdx.x * 128;
    u32 as_base = (u32)__cvta_generic_to_shared(&As[0][0]);
    u32 bs_base = (u32)__cvta_generic_to_shared(&Bs[0][0]);

    float acc[20];
#pragma unroll
    for (int i = 0; i < 20; i++) acc[i] = 0.f;

    for (int k0 = 0; k0 < 128; k0 += 16) {
        {
            int row = tid >> 1;
            int kp = (tid & 1) * 8;
            int grow = row0 + row;
            float4 v0 = make_float4(0.f, 0.f, 0.f, 0.f);
            float4 v1 = v0;
            if (grow < NN) {
                v0 = *(const float4*)&g_out1[grow * 128 + k0 + kp];
                v1 = *(const float4*)&g_out1[grow * 128 + k0 + kp + 4];
            }
            __half2 hh[4];
            hh[0] = __floats2half2_rn(v0.x, v0.y);
            hh[1] = __floats2half2_rn(v0.z, v0.w);
            hh[2] = __floats2half2_rn(v1.x, v1.y);
            hh[3] = __floats2half2_rn(v1.z, v1.w);
            *(uint4*)&As[row][kp] = *(uint4*)hh;
        }
        if (tid < 160) {
            int k = tid / 10;
            int nc = (tid % 10) * 4;
            float4 w = *(const float4*)&B[(k0 + k) * 40 + nc];
            __half2 h0 = __floats2half2_rn(w.x, w.y);
            __half2 h1 = __floats2half2_rn(w.z, w.w);
            uint2 p;
            p.x = *(u32*)&h0;
            p.y = *(u32*)&h1;
            *(uint2*)&Bs[k][nc] = p;
        }
        __syncthreads();
        u32 a0[4];
        ldsm_x4(a0[0], a0[1], a0[2], a0[3],
                as_base + (u32)(m0 + (lane & 15)) * 48u + (u32)(lane >> 4) * 16u);
#pragma unroll
        for (int t = 0; t < 5; t++) {
            u32 b0, b1;
            ldsm_x2_t(b0, b1, bs_base + (u32)(lane & 15) * 144u + (u32)(t * 8) * 2u);
            mma16816(&acc[t * 4], a0, b0, b1);
        }
        __syncthreads();
    }

    int g = lane >> 2;
    int q = lane & 3;
    int r0 = row0 + m0 + g;
    int r1 = r0 + 8;
    float ps0 = 0.f;
    float ps1 = 0.f;
    float pd0 = 0.f;
    float pd1 = 0.f;
#pragma unroll
    for (int t = 0; t < 5; t++) {
        float* c = &acc[t * 4];
        int col = t * 8 + q * 2;
        float w0 = att_src[col];
        float w1 = att_src[col + 1];
        float v0 = att_dst[col];
        float v1 = att_dst[col + 1];
        ps0 += c[0] * w0 + c[1] * w1;
        pd0 += c[0] * v0 + c[1] * v1;
        ps1 += c[2] * w0 + c[3] * w1;
        pd1 += c[2] * v0 + c[3] * v1;
        int h2i = t * 4 + q;
        if (r0 < NN) g_h2h[r0 * 20 + h2i] = __floats2half2_rn(c[0], c[1]);
        if (r1 < NN) g_h2h[r1 * 20 + h2i] = __floats2half2_rn(c[2], c[3]);
    }
    ps0 += __shfl_xor_sync(0xffffffffu, ps0, 1);
    ps0 += __shfl_xor_sync(0xffffffffu, ps0, 2);
    ps1 += __shfl_xor_sync(0xffffffffu, ps1, 1);
    ps1 += __shfl_xor_sync(0xffffffffu, ps1, 2);
    pd0 += __shfl_xor_sync(0xffffffffu, pd0, 1);
    pd0 += __shfl_xor_sync(0xffffffffu, pd0, 2);
    pd1 += __shfl_xor_sync(0xffffffffu, pd1, 1);
    pd1 += __shfl_xor_sync(0xffffffffu, pd1, 2);
    if (q == 0) {
        if (r0 < NN) { g_as2[r0] = ps0; g_ad2[r0] = pd0; }
        if (r1 < NN) { g_as2[r1] = ps1; g_ad2[r1] = pd1; }
    }
}

// ---------------- layer2 node kernel: 3 edges/iteration, fp16 gather -------------
__global__ void k_node2(const float* __restrict__ b2, float* __restrict__ dout) {
    int lane = threadIdx.x & 31;
    int warp = (blockIdx.x * blockDim.x + threadIdx.x) >> 5;
    int nwarp = (gridDim.x * blockDim.x) >> 5;
    int grp = lane / 10;
    int cl = lane - grp * 10;
    for (int n = warp; n < NN; n += nwarp) {
        int cnt = g_cnt[n];
        if (cnt > CAP) cnt = CAP;
        int beg = n * CAP;
        float ad = g_ad2[n];
        float ax = 0.f;
        float ay = 0.f;
        float az = 0.f;
        float aw = 0.f;
        float sum = 0.f;
        for (int base = 0; base < cnt; base += 32) {
            int c = cnt - base;
            if (c > 32) c = 32;
            int idx = (lane < c) ? g_bkt[beg + base + lane] : 0;
            float el = 0.f;
            if (lane < c) el = __expf(leaky(g_as2[idx] + ad));
            float tot = el;
            tot += __shfl_xor_sync(0xffffffffu, tot, 16);
            tot += __shfl_xor_sync(0xffffffffu, tot, 8);
            tot += __shfl_xor_sync(0xffffffffu, tot, 4);
            tot += __shfl_xor_sync(0xffffffffu, tot, 2);
            tot += __shfl_xor_sync(0xffffffffu, tot, 1);
            sum += tot;
            for (int j = 0; j < c; j += 3) {
                int eIdx = j + grp;
                int src = (eIdx < 32) ? eIdx : 0;
                int s = __shfl_sync(0xffffffffu, idx, src);
                float e = __shfl_sync(0xffffffffu, el, src);
                if (grp < 3 && eIdx < c) {
                    uint2 raw = *(const uint2*)&g_h2h[s * 20 + cl * 2];
                    float2 f0 = __half22float2(*(const __half2*)&raw.x);
                    float2 f1 = __half22float2(*(const __half2*)&raw.y);
                    ax += e * f0.x;
                    ay += e * f0.y;
                    az += e * f1.x;
                    aw += e * f1.y;
                }
            }
        }
        ax += __shfl_sync(0xffffffffu, ax, lane + 10) + __shfl_sync(0xffffffffu, ax, lane + 20);
        ay += __shfl_sync(0xffffffffu, ay, lane + 10) + __shfl_sync(0xffffffffu, ay, lane + 20);
        az += __shfl_sync(0xffffffffu, az, lane + 10) + __shfl_sync(0xffffffffu, az, lane + 20);
        aw += __shfl_sync(0xffffffffu, aw, lane + 10) + __shfl_sync(0xffffffffu, aw, lane + 20);
        float inv = (sum > 0.f) ? 1.f / sum : 0.f;
        if (lane < 10) {
            float4 bv = *(const float4*)&b2[lane * 4];
            float4 o;
            o.x = ax * inv + bv.x;
            o.y = ay * inv + bv.y;
            o.z = az * inv + bv.z;
            o.w = aw * inv + bv.w;
            *(float4*)&dout[n * 40 + lane * 4] = o;
        }
        if (lane == 0) g_cnt[n] = 0;
    }
}

// ---------------- launch ----------------
extern "C" void kernel_launch(void* const* d_in, const int* in_sizes, int n_in,
                              void* d_out, int out_size) {
    const float* x   = (const float*)d_in[0];
    const int*   ei  = (const int*)d_in[1];
    const float* W1  = (const float*)d_in[2];
    const float* as1 = (const float*)d_in[3];
    const float* ad1 = (const float*)d_in[4];
    const float* b1  = (const float*)d_in[5];
    const float* W2  = (const float*)d_in[6];
    const float* as2 = (const float*)d_in[7];
    const float* ad2 = (const float*)d_in[8];
    const float* b2  = (const float*)d_in[9];
    float* out = (float*)d_out;

    k_fat<<<GB1 + (NE + 255) / 256, 256>>>(x, W1, as1, ad1, ei);
    k_node1<<<(NN * 32 + 255) / 256, 256>>>(b1);
    k_gemm2<<<(NN + 127) / 128, 256>>>(W2, as2, ad2);
    k_node2<<<(NN * 32 + 255) / 256, 256>>>(b2, out);
}